// round 9
// baseline (speedup 1.0000x reference)
#include <cuda_runtime.h>
#include <cuda_fp16.h>
#include <cstdint>

// Shapes (fixed by the problem)
#define BB 8192            // batch (GEMM M)
#define II 512             // input dim
#define FF 64              // freqs
#define OO 512             // output dim (GEMM N)
#define KK (II * FF)       // GEMM K = 32768

// GEMM tiling: 2 CTAs/SM for cross-CTA latency hiding
#define BM 128
#define BN 128
#define BK 64              // one i-column of x per K iteration
#define NTHREADS 256
#define A_STRIDE 72        // halves: 144B rows, conflict-free ldmatrix
#define W_STRIDE 136       // halves: 272B rows (128 + 8 pad)
#define KITERS (KK / BK)   // 512

// ---- device scratch (allocation-free rule: __device__ globals) ----
__device__ __half g_W[(size_t)KK * OO]; // 32 MB: W[k][o] = inv_f*beta[f,o]*lamb[i,o]
__device__ float  g_xT[(size_t)II * BB];// 16 MB: x transposed [I][B]
__device__ float  g_biasp[OO];          // folded bias

// ---------------- merged prologue ----------------
// blocks [0,4096):    build W (16 halves / thread)
// blocks [4096,8192): transpose x -> xT
// blocks [8192,8194): folded bias
__global__ void k_prep(const float* __restrict__ x,
                       const float* __restrict__ freqs,
                       const float* __restrict__ phases,
                       const float* __restrict__ beta,
                       const float* __restrict__ lamb,
                       const float* __restrict__ bias) {
    const int bx = blockIdx.x;
    const int t  = threadIdx.x;

    if (bx < 4096) {
        __shared__ float sinv[FF];
        if (t < FF) {
            float w = freqs[t], p = phases[t];
            float m = expf(-0.5f * w * w) * sinf(p);
            float v = 0.5f - 0.5f * expf(-2.0f * w * w) * cosf(2.0f * p) - m * m;
            sinv[t] = rsqrtf(1e-3f + v);
        }
        __syncthreads();
        size_t base = ((size_t)bx * 256 + t) * 16;   // 16 consecutive o, same k
        int k = (int)(base >> 9);
        int o = (int)(base & 511);
        int f = k & (FF - 1);
        int i = k >> 6;
        float inv = sinv[f];
        const float4* b4 = (const float4*)(beta + (size_t)f * OO + o);
        const float4* l4 = (const float4*)(lamb + (size_t)i * OO + o);
        __half2 h[8];
        #pragma unroll
        for (int j = 0; j < 4; j++) {
            float4 bb = b4[j], ll = l4[j];
            h[2 * j]     = __floats2half2_rn(inv * bb.x * ll.x, inv * bb.y * ll.y);
            h[2 * j + 1] = __floats2half2_rn(inv * bb.z * ll.z, inv * bb.w * ll.w);
        }
        *(uint4*)(g_W + base)     = *(uint4*)(h);
        *(uint4*)(g_W + base + 8) = *(uint4*)(h + 4);
    } else if (bx < 8192) {
        __shared__ float tile[32][33];
        int bx2 = bx - 4096;
        int i0 = (bx2 & 15) * 32;
        int b0 = (bx2 >> 4) * 32;
        int tx = t & 31, ty = t >> 5;
        #pragma unroll
        for (int j = 0; j < 4; j++)
            tile[ty + j * 8][tx] = x[(size_t)(b0 + ty + j * 8) * II + i0 + tx];
        __syncthreads();
        #pragma unroll
        for (int j = 0; j < 4; j++)
            g_xT[(size_t)(i0 + ty + j * 8) * BB + b0 + tx] = tile[tx][ty + j * 8];
    } else {
        __shared__ float smv[FF];
        if (t < FF) {
            float w = freqs[t], p = phases[t];
            float m = expf(-0.5f * w * w) * sinf(p);
            float v = 0.5f - 0.5f * expf(-2.0f * w * w) * cosf(2.0f * p) - m * m;
            smv[t] = m * rsqrtf(1e-3f + v);
        }
        __syncthreads();
        int o = (bx - 8192) * 256 + t;
        float s1 = 0.f;
        #pragma unroll
        for (int f = 0; f < FF; f++) s1 += smv[f] * beta[f * OO + o];
        float s2 = 0.f;
        for (int i = 0; i < II; i++) s2 += lamb[(size_t)i * OO + o];
        g_biasp[o] = bias[o] - s1 * s2;
    }
}

// ---------------- helpers ----------------
__device__ __forceinline__ void cp_async16(void* s, const void* g) {
    uint32_t sa = (uint32_t)__cvta_generic_to_shared(s);
    asm volatile("cp.async.cg.shared.global [%0], [%1], 16;\n" :: "r"(sa), "l"(g));
}
__device__ __forceinline__ uint32_t smem_u32(const void* p) {
    return (uint32_t)__cvta_generic_to_shared(p);
}

// W tile: 64 rows x 128 o = 16KB = 1024 x 16B chunks, 4 per thread
__device__ __forceinline__ void issueW(int k, int t, int bn0, __half* sW) {
    const int buf = k & 1;
    const __half* gW = g_W + (size_t)k * (BK * OO) + bn0;
    __half* sWb = sW + buf * (BK * W_STRIDE);
    #pragma unroll
    for (int j = 0; j < 4; j++) {
        int c = t + NTHREADS * j;      // 0..1023: 64 rows x 16 chunks
        int row = c >> 4;
        int seg = c & 15;
        cp_async16(sWb + row * W_STRIDE + seg * 8, gW + (size_t)row * OO + seg * 8);
    }
    asm volatile("cp.async.commit_group;\n" ::: "memory");
}

__global__ __launch_bounds__(NTHREADS, 2)
void k_gemm(float* __restrict__ out,
            const float* __restrict__ freqs, const float* __restrict__ phases) {
    extern __shared__ char smem_raw[];
    __half* sA = (__half*)smem_raw;                      // [2][BM][A_STRIDE]
    __half* sW = sA + 2 * BM * A_STRIDE;                 // [2][BK][W_STRIDE]
    float* swf = (float*)(sW + 2 * BK * W_STRIDE);       // [FF]
    float* spf = swf + FF;                               // [FF]

    const int t    = threadIdx.x;
    const int lane = t & 31;
    const int warp = t >> 5;                 // 0..7
    const int bm0  = blockIdx.y * BM;
    const int bn0  = blockIdx.x * BN;
    const int wm0  = (warp >> 1) * 32;       // 4 warp-rows of 32
    const int wn0  = (warp & 1) * 64;        // 2 warp-cols of 64

    const int gr  = t >> 1;                  // A row this thread generates
    const int gfb = (t & 1) * 32;            // 32-freq half

    if (t < FF) { swf[t] = freqs[t]; spf[t] = phases[t]; }

    float acc[2][8][4];
    #pragma unroll
    for (int mt = 0; mt < 2; mt++)
        #pragma unroll
        for (int nt = 0; nt < 8; nt++)
            #pragma unroll
            for (int r = 0; r < 4; r++) acc[mt][nt][r] = 0.f;

    issueW(0, t, bn0, sW);
    __syncthreads();                         // swf/spf visible

    // gen A(0) into buf 0, prefetch x(1)
    float xv = g_xT[(size_t)0 * BB + bm0 + gr];
    {
        __half* aRow = sA + (size_t)gr * A_STRIDE + gfb;
        #pragma unroll
        for (int c = 0; c < 4; c++) {
            __half2 h[4];
            #pragma unroll
            for (int j = 0; j < 4; j++) {
                int f = gfb + c * 8 + 2 * j;
                h[j] = __floats2half2_rn(__sinf(fmaf(swf[f],     xv, spf[f])),
                                         __sinf(fmaf(swf[f + 1], xv, spf[f + 1])));
            }
            *(uint4*)(aRow + c * 8) = *(uint4*)h;
        }
    }
    xv = g_xT[(size_t)1 * BB + bm0 + gr];

    for (int k = 0; k < KITERS; k++) {
        const int buf = k & 1;
        asm volatile("cp.async.wait_group 0;\n" ::: "memory");  // W(k) landed
        __syncthreads();   // W(k) + A(k) visible; buffers buf^1 free

        if (k + 1 < KITERS) issueW(k + 1, t, bn0, sW);

        // ---- MMA batch for slab k ----
        const __half* Ab = sA + buf * (BM * A_STRIDE);
        const __half* Wb = sW + buf * (BK * W_STRIDE);
        #pragma unroll
        for (int ks = 0; ks < 4; ks++) {
            uint32_t af[2][4];
            #pragma unroll
            for (int mt = 0; mt < 2; mt++) {
                uint32_t addr = smem_u32(Ab + (size_t)(wm0 + mt * 16 + (lane & 15)) * A_STRIDE
                                            + ks * 16 + (lane >> 4) * 8);
                asm volatile("ldmatrix.sync.aligned.m8n8.x4.shared.b16 {%0,%1,%2,%3}, [%4];\n"
                    : "=r"(af[mt][0]), "=r"(af[mt][1]), "=r"(af[mt][2]), "=r"(af[mt][3])
                    : "r"(addr));
            }
            uint32_t bf[8][2];
            #pragma unroll
            for (int np = 0; np < 4; np++) {
                uint32_t addr = smem_u32(Wb + (size_t)(ks * 16 + (lane & 15)) * W_STRIDE
                                            + wn0 + np * 16 + (lane >> 4) * 8);
                uint32_t b0, b1, b2, b3;
                asm volatile("ldmatrix.sync.aligned.m8n8.x4.trans.shared.b16 {%0,%1,%2,%3}, [%4];\n"
                    : "=r"(b0), "=r"(b1), "=r"(b2), "=r"(b3) : "r"(addr));
                bf[np * 2][0] = b0;     bf[np * 2][1] = b1;
                bf[np * 2 + 1][0] = b2; bf[np * 2 + 1][1] = b3;
            }
            #pragma unroll
            for (int mt = 0; mt < 2; mt++)
                #pragma unroll
                for (int nt = 0; nt < 8; nt++) {
                    asm volatile(
                        "mma.sync.aligned.m16n8k16.row.col.f32.f16.f16.f32 "
                        "{%0,%1,%2,%3}, {%4,%5,%6,%7}, {%8,%9}, {%0,%1,%2,%3};\n"
                        : "+f"(acc[mt][nt][0]), "+f"(acc[mt][nt][1]),
                          "+f"(acc[mt][nt][2]), "+f"(acc[mt][nt][3])
                        : "r"(af[mt][0]), "r"(af[mt][1]), "r"(af[mt][2]), "r"(af[mt][3]),
                          "r"(bf[nt][0]), "r"(bf[nt][1]));
                }
        }

        // ---- overlap: gen A(k+1) into other buffer (MUFU hides under HMMA) ----
        if (k + 1 < KITERS) {
            __half* aRow = sA + (buf ^ 1) * (BM * A_STRIDE) + (size_t)gr * A_STRIDE + gfb;
            #pragma unroll
            for (int c = 0; c < 4; c++) {
                __half2 h[4];
                #pragma unroll
                for (int j = 0; j < 4; j++) {
                    int f = gfb + c * 8 + 2 * j;
                    h[j] = __floats2half2_rn(__sinf(fmaf(swf[f],     xv, spf[f])),
                                             __sinf(fmaf(swf[f + 1], xv, spf[f + 1])));
                }
                *(uint4*)(aRow + c * 8) = *(uint4*)h;
            }
            if (k + 2 < KITERS)
                xv = g_xT[(size_t)(k + 2) * BB + bm0 + gr];
        }
    }

    // ---- epilogue: add folded bias, store fp32 ----
    #pragma unroll
    for (int mt = 0; mt < 2; mt++) {
        int row = bm0 + wm0 + mt * 16 + (lane >> 2);
        #pragma unroll
        for (int nt = 0; nt < 8; nt++) {
            int col = bn0 + wn0 + nt * 8 + (lane & 3) * 2;
            float b0 = g_biasp[col], b1 = g_biasp[col + 1];
            float2 v0 = make_float2(acc[mt][nt][0] + b0, acc[mt][nt][1] + b1);
            float2 v1 = make_float2(acc[mt][nt][2] + b0, acc[mt][nt][3] + b1);
            *(float2*)(out + (size_t)row * OO + col)       = v0;
            *(float2*)(out + (size_t)(row + 8) * OO + col) = v1;
        }
    }
}

// ---------------- launch ----------------
extern "C" void kernel_launch(void* const* d_in, const int* in_sizes, int n_in,
                              void* d_out, int out_size) {
    const float* x      = (const float*)d_in[0];  // [8192, 512]
    const float* freqs  = (const float*)d_in[1];  // [1,1,64]
    const float* phases = (const float*)d_in[2];  // [1,1,64]
    const float* beta   = (const float*)d_in[3];  // [64, 512]
    const float* lamb   = (const float*)d_in[4];  // [512, 512]
    const float* bias   = (const float*)d_in[5];  // [512]
    float* out = (float*)d_out;                   // [8192, 512] fp32

    k_prep<<<8194, 256>>>(x, freqs, phases, beta, lamb, bias);

    const size_t smem_bytes =
        (size_t)(2 * BM * A_STRIDE + 2 * BK * W_STRIDE) * sizeof(__half)
        + (size_t)(2 * FF) * sizeof(float);   // 72,192 B per CTA (x2 CTAs/SM = 144KB)
    cudaFuncSetAttribute(k_gemm, cudaFuncAttributeMaxDynamicSharedMemorySize,
                         (int)smem_bytes);
    dim3 grid(OO / BN, BB / BM);   // (4, 64) = 256 CTAs -> 2 per SM
    k_gemm<<<grid, NTHREADS, smem_bytes>>>(out, freqs, phases);
}